// round 1
// baseline (speedup 1.0000x reference)
#include <cuda_runtime.h>
#include <math.h>

#define BB 2
#define SS 2048
#define EE 768
#define HH 12
#define DK 64

// Scratch (allocation-free: __device__ globals)
__device__ float g_Q[BB*HH*SS*DK];   // [B,H,S,Dk]
__device__ float g_K[BB*HH*SS*DK];
__device__ float g_V[BB*HH*SS*DK];
__device__ float g_C[BB*SS*EE];      // concat [B,S,H*Dk]

// ---------------------------------------------------------------------------
// Per-head projection GEMM: for (b,h,tile): C[64,64] = X[64x768] * W_h[768x64]
// grid = (S/64, H, B), block = 256
// ---------------------------------------------------------------------------
__global__ __launch_bounds__(256) void proj_kernel(
    const float* __restrict__ X, const float* __restrict__ Wt, int which)
{
    int tile = blockIdx.x, h = blockIdx.y, b = blockIdx.z;
    float* Out = (which == 0) ? g_Q : (which == 1) ? g_K : g_V;

    const float* A  = X  + (size_t)(b*SS + tile*64) * EE;
    const float* Bw = Wt + (size_t)h * EE * DK;
    float*       C  = Out + (size_t)((b*HH + h)*SS + tile*64) * DK;

    __shared__ float As[16][64];   // transposed A tile: As[k][m]
    __shared__ float Bs[16][64];   // Bs[k][n]

    int tid = threadIdx.x;
    int tx = tid & 15, ty = tid >> 4;
    float acc[4][4] = {};

    for (int k0 = 0; k0 < EE; k0 += 16) {
        #pragma unroll
        for (int i = 0; i < 4; i++) {
            int idx = tid + i * 256;
            int m = idx >> 4, kk = idx & 15;
            As[kk][m] = A[m * EE + k0 + kk];
        }
        #pragma unroll
        for (int i = 0; i < 4; i++) {
            int idx = tid + i * 256;
            int kk = idx >> 6, n = idx & 63;
            Bs[kk][n] = Bw[(k0 + kk) * DK + n];
        }
        __syncthreads();
        #pragma unroll
        for (int k = 0; k < 16; k++) {
            float4 a4 = *(const float4*)&As[k][ty * 4];
            float4 b4 = *(const float4*)&Bs[k][tx * 4];
            float av[4] = {a4.x, a4.y, a4.z, a4.w};
            float bv[4] = {b4.x, b4.y, b4.z, b4.w};
            #pragma unroll
            for (int i = 0; i < 4; i++)
                #pragma unroll
                for (int j = 0; j < 4; j++)
                    acc[i][j] += av[i] * bv[j];
        }
        __syncthreads();
    }
    #pragma unroll
    for (int i = 0; i < 4; i++)
        #pragma unroll
        for (int j = 0; j < 4; j++)
            C[(ty*4 + i) * DK + tx*4 + j] = acc[i][j];
}

// ---------------------------------------------------------------------------
// Flash attention with mask. grid = (S/64, H, B), block = 64 (1 thread = 1 row)
// Writes result directly into concat layout g_C[B,S,H*Dk].
// ---------------------------------------------------------------------------
__global__ __launch_bounds__(64) void flash_kernel(const int* __restrict__ mask)
{
    int qt = blockIdx.x, h = blockIdx.y, b = blockIdx.z;
    int r = threadIdx.x;  // query row within tile, 0..63

    __shared__ float Qs[64][68];   // padded: float4-aligned, conflict-spread
    __shared__ float Ks[32][64];
    __shared__ float Vs[32][64];
    __shared__ int   Ms[64][32];

    const float* Qp = g_Q + (size_t)((b*HH + h)*SS + qt*64) * DK;
    const float* Kp = g_K + (size_t)(b*HH + h) * SS * DK;
    const float* Vp = g_V + (size_t)(b*HH + h) * SS * DK;
    const int*   Mp = mask + (size_t)(b*SS + qt*64) * SS;

    // load Q tile (coalesced: thread r loads column r of each row)
    for (int i = 0; i < 64; i++) Qs[i][r] = Qp[i * DK + r];

    float m_i = -INFINITY, l_i = 0.f;
    float acc[64];
    #pragma unroll
    for (int d = 0; d < 64; d++) acc[d] = 0.f;

    for (int kt = 0; kt < SS / 32; kt++) {
        __syncthreads();
        for (int i = 0; i < 32; i++) {
            Ks[i][r] = Kp[(kt*32 + i) * DK + r];
            Vs[i][r] = Vp[(kt*32 + i) * DK + r];
        }
        for (int idx = r; idx < 64 * 32; idx += 64) {
            int rr = idx >> 5, cc = idx & 31;
            Ms[rr][cc] = Mp[rr * SS + kt*32 + cc];
        }
        __syncthreads();

        // scores: s[j] = Q_row . K_j
        float s[32];
        #pragma unroll
        for (int j = 0; j < 32; j++) s[j] = 0.f;
        #pragma unroll
        for (int k = 0; k < 64; k += 4) {
            float4 q4 = *(const float4*)&Qs[r][k];
            #pragma unroll
            for (int j = 0; j < 32; j++) {
                float4 k4 = *(const float4*)&Ks[j][k];
                s[j] += q4.x*k4.x + q4.y*k4.y + q4.z*k4.z + q4.w*k4.w;
            }
        }

        // scale + mask, running max
        float mt = m_i;
        #pragma unroll
        for (int j = 0; j < 32; j++) {
            s[j] = Ms[r][j] ? s[j] * 0.125f : -1e9f;
            mt = fmaxf(mt, s[j]);
        }

        float corr = __expf(m_i - mt);   // 0 when m_i == -inf
        l_i *= corr;
        #pragma unroll
        for (int d = 0; d < 64; d++) acc[d] *= corr;

        #pragma unroll
        for (int j = 0; j < 32; j++) {
            float p = __expf(s[j] - mt);
            l_i += p;
            #pragma unroll
            for (int d = 0; d < 64; d += 4) {
                float4 v4 = *(const float4*)&Vs[j][d];
                acc[d+0] += p * v4.x;
                acc[d+1] += p * v4.y;
                acc[d+2] += p * v4.z;
                acc[d+3] += p * v4.w;
            }
        }
        m_i = mt;
    }

    float inv = 1.f / l_i;
    float* Cp = g_C + (size_t)(b*SS + qt*64 + r) * EE + h * DK;
    #pragma unroll
    for (int d = 0; d < 64; d++) Cp[d] = acc[d] * inv;
}

// ---------------------------------------------------------------------------
// Output projection: out[4096,768] = g_C[4096,768] @ W[768,768]
// grid = (M/64, N/64) = (64, 12), block = 256
// ---------------------------------------------------------------------------
__global__ __launch_bounds__(256) void out_proj_kernel(
    const float* __restrict__ W, float* __restrict__ outp)
{
    int mt = blockIdx.x, nt = blockIdx.y;
    const float* A = g_C + (size_t)mt * 64 * EE;
    const float* Bw = W + nt * 64;
    float* C = outp + (size_t)mt * 64 * EE + nt * 64;

    __shared__ float As[16][64];
    __shared__ float Bs[16][64];

    int tid = threadIdx.x;
    int tx = tid & 15, ty = tid >> 4;
    float acc[4][4] = {};

    for (int k0 = 0; k0 < EE; k0 += 16) {
        #pragma unroll
        for (int i = 0; i < 4; i++) {
            int idx = tid + i * 256;
            int m = idx >> 4, kk = idx & 15;
            As[kk][m] = A[m * EE + k0 + kk];
        }
        #pragma unroll
        for (int i = 0; i < 4; i++) {
            int idx = tid + i * 256;
            int kk = idx >> 6, n = idx & 63;
            Bs[kk][n] = Bw[(k0 + kk) * EE + n];
        }
        __syncthreads();
        #pragma unroll
        for (int k = 0; k < 16; k++) {
            float4 a4 = *(const float4*)&As[k][ty * 4];
            float4 b4 = *(const float4*)&Bs[k][tx * 4];
            float av[4] = {a4.x, a4.y, a4.z, a4.w};
            float bv[4] = {b4.x, b4.y, b4.z, b4.w};
            #pragma unroll
            for (int i = 0; i < 4; i++)
                #pragma unroll
                for (int j = 0; j < 4; j++)
                    acc[i][j] += av[i] * bv[j];
        }
        __syncthreads();
    }
    #pragma unroll
    for (int i = 0; i < 4; i++)
        #pragma unroll
        for (int j = 0; j < 4; j++)
            C[(ty*4 + i) * EE + tx*4 + j] = acc[i][j];
}

// ---------------------------------------------------------------------------
extern "C" void kernel_launch(void* const* d_in, const int* in_sizes, int n_in,
                              void* d_out, int out_size)
{
    const float* q    = (const float*)d_in[0];
    const float* k    = (const float*)d_in[1];
    const float* v    = (const float*)d_in[2];
    const int*   mask = (const int*)  d_in[3];
    const float* Wq   = (const float*)d_in[4];
    const float* Wk   = (const float*)d_in[5];
    const float* Wv   = (const float*)d_in[6];
    const float* W    = (const float*)d_in[7];
    float* out = (float*)d_out;

    dim3 gp(SS / 64, HH, BB);
    proj_kernel<<<gp, 256>>>(q, Wq, 0);
    proj_kernel<<<gp, 256>>>(k, Wk, 1);
    proj_kernel<<<gp, 256>>>(v, Wv, 2);

    flash_kernel<<<dim3(SS / 64, HH, BB), 64>>>(mask);

    out_proj_kernel<<<dim3((BB * SS) / 64, EE / 64), 256>>>(W, out);
}